// round 8
// baseline (speedup 1.0000x reference)
#include <cuda_runtime.h>

// GRU: I=2, H=2, T=512, B=32768, single layer, then out = exp(fc(h_t)) per step.
// One thread per batch lane; serial scan over T with double-buffered register
// prefetch of x. Output buffer layout: [T*B] outputs, then [B*2] final h.

#define TT 512
#define BB 32768
#define CH 16           // prefetch chunk (timesteps)
#define L2E 1.4426950408889634f

__device__ __forceinline__ float rcp_fast(float x) {
    float y; asm("rcp.approx.f32 %0, %1;" : "=f"(y) : "f"(x)); return y;
}
__device__ __forceinline__ float ex2_fast(float x) {
    float y; asm("ex2.approx.f32 %0, %1;" : "=f"(y) : "f"(x)); return y;
}
// sigmoid(a) = 1/(1+2^(-a*log2e)) : 2 MUFU, ~2^-22 accurate, saturates safely.
__device__ __forceinline__ float sigmoid_f(float a) {
    return rcp_fast(1.0f + ex2_fast(-L2E * a));
}
// tanh(a) = 2*sigmoid(2a)-1 : safe at extremes (no inf/inf), ~1e-7 abs err.
__device__ __forceinline__ float tanh_f(float a) {
    return fmaf(2.0f, rcp_fast(1.0f + ex2_fast(-2.0f * L2E * a)), -1.0f);
}

// PyTorch gate order in the 3H dim: rows 0,1 = r ; 2,3 = z ; 4,5 = n.
#define GRU_STEP(x0, x1, OIDX) do {                                   \
    /* off-chain: input projections (b_ih folded; r,z also get b_hh) */\
    float ur0  = fmaf(wi00, x0, fmaf(wi01, x1, bs0));                 \
    float ur1  = fmaf(wi10, x0, fmaf(wi11, x1, bs1));                 \
    float uz0  = fmaf(wi20, x0, fmaf(wi21, x1, bs2));                 \
    float uz1  = fmaf(wi30, x0, fmaf(wi31, x1, bs3));                 \
    float gin0 = fmaf(wi40, x0, fmaf(wi41, x1, bin0));                \
    float gin1 = fmaf(wi50, x0, fmaf(wi51, x1, bin1));                \
    /* on-chain: hidden projections */                                \
    float ar0  = fmaf(wh00, h0, fmaf(wh01, h1, ur0));                 \
    float ar1  = fmaf(wh10, h0, fmaf(wh11, h1, ur1));                 \
    float az0  = fmaf(wh20, h0, fmaf(wh21, h1, uz0));                 \
    float az1  = fmaf(wh30, h0, fmaf(wh31, h1, uz1));                 \
    float ghn0 = fmaf(wh40, h0, fmaf(wh41, h1, bhn0));                \
    float ghn1 = fmaf(wh50, h0, fmaf(wh51, h1, bhn1));                \
    float r0 = sigmoid_f(ar0);                                        \
    float r1 = sigmoid_f(ar1);                                        \
    float z0 = sigmoid_f(az0);                                        \
    float z1 = sigmoid_f(az1);                                        \
    float n0 = tanh_f(fmaf(r0, ghn0, gin0));                          \
    float n1 = tanh_f(fmaf(r1, ghn1, gin1));                          \
    /* h = (1-z)*n + z*h  ==  n + z*(h-n) */                          \
    h0 = fmaf(z0, h0 - n0, n0);                                       \
    h1 = fmaf(z1, h1 - n1, n1);                                       \
    /* out = exp(fc_w . h + fc_b) via ex2 with prescaled constants */ \
    out[(size_t)(OIDX) * BB + b] =                                    \
        ex2_fast(fmaf(fw0, h0, fmaf(fw1, h1, fb)));                   \
} while (0)

__global__ void __launch_bounds__(64)
gru_scan_kernel(const float* __restrict__ x,
                const float* __restrict__ hx,
                const float* __restrict__ W_ih,
                const float* __restrict__ W_hh,
                const float* __restrict__ b_ih,
                const float* __restrict__ b_hh,
                const float* __restrict__ fc_w,
                const float* __restrict__ fc_b,
                float* __restrict__ out)
{
    const int b = blockIdx.x * 64 + threadIdx.x;   // batch lane

    // Uniform-address weight loads (broadcast, hit L1 after first warp).
    const float wi00 = W_ih[0],  wi01 = W_ih[1];
    const float wi10 = W_ih[2],  wi11 = W_ih[3];
    const float wi20 = W_ih[4],  wi21 = W_ih[5];
    const float wi30 = W_ih[6],  wi31 = W_ih[7];
    const float wi40 = W_ih[8],  wi41 = W_ih[9];
    const float wi50 = W_ih[10], wi51 = W_ih[11];

    const float wh00 = W_hh[0],  wh01 = W_hh[1];
    const float wh10 = W_hh[2],  wh11 = W_hh[3];
    const float wh20 = W_hh[4],  wh21 = W_hh[5];
    const float wh30 = W_hh[6],  wh31 = W_hh[7];
    const float wh40 = W_hh[8],  wh41 = W_hh[9];
    const float wh50 = W_hh[10], wh51 = W_hh[11];

    const float bs0  = b_ih[0] + b_hh[0];   // r0: biases fold into preact
    const float bs1  = b_ih[1] + b_hh[1];   // r1
    const float bs2  = b_ih[2] + b_hh[2];   // z0
    const float bs3  = b_ih[3] + b_hh[3];   // z1
    const float bin0 = b_ih[4], bin1 = b_ih[5];   // n: b_ih outside r*
    const float bhn0 = b_hh[4], bhn1 = b_hh[5];   // n: b_hh inside r*

    // exp(fc.h + fb) = 2^((fc.h + fb)*log2e) — prescale constants.
    const float fw0 = fc_w[0] * L2E;
    const float fw1 = fc_w[1] * L2E;
    const float fb  = fc_b[0] * L2E;

    const float2 hinit = reinterpret_cast<const float2*>(hx)[b];
    float h0 = hinit.x, h1 = hinit.y;

    const float2* __restrict__ x2 = reinterpret_cast<const float2*>(x);

    // Double-buffered register prefetch: hide ~600-1000cyc DRAM latency behind
    // ~1000cyc of compute per 16-step chunk. MLP=16 per warp.
    float2 bufA[CH], bufB[CH];
#pragma unroll
    for (int i = 0; i < CH; i++) bufA[i] = x2[(size_t)i * BB + b];

    for (int tc = 0; tc < TT; tc += 2 * CH) {
#pragma unroll
        for (int i = 0; i < CH; i++)
            bufB[i] = x2[(size_t)(tc + CH + i) * BB + b];

#pragma unroll
        for (int i = 0; i < CH; i++) {
            float x0 = bufA[i].x, x1 = bufA[i].y;
            GRU_STEP(x0, x1, tc + i);
        }

        if (tc + 2 * CH < TT) {
#pragma unroll
            for (int i = 0; i < CH; i++)
                bufA[i] = x2[(size_t)(tc + 2 * CH + i) * BB + b];
        }

#pragma unroll
        for (int i = 0; i < CH; i++) {
            float x0 = bufB[i].x, x1 = bufB[i].y;
            GRU_STEP(x0, x1, tc + CH + i);
        }
    }

    // Final hidden state appended after the [T*B] output block.
    reinterpret_cast<float2*>(out + (size_t)TT * BB)[b] = make_float2(h0, h1);
}

extern "C" void kernel_launch(void* const* d_in, const int* in_sizes, int n_in,
                              void* d_out, int out_size)
{
    const float* x    = (const float*)d_in[0];
    const float* hx   = (const float*)d_in[1];
    const float* W_ih = (const float*)d_in[2];
    const float* W_hh = (const float*)d_in[3];
    const float* b_ih = (const float*)d_in[4];
    const float* b_hh = (const float*)d_in[5];
    const float* fc_w = (const float*)d_in[6];
    const float* fc_b = (const float*)d_in[7];
    float* out = (float*)d_out;

    gru_scan_kernel<<<BB / 64, 64>>>(x, hx, W_ih, W_hh, b_ih, b_hh,
                                     fc_w, fc_b, out);
}

// round 11
// speedup vs baseline: 1.5019x; 1.5019x over previous
#include <cuda_runtime.h>

// GRU: I=2, H=2, T=512, B=32768, single layer, then out = exp(fc(h_t)) per step.
// One thread per batch lane; serial scan over T with double-buffered register
// prefetch of x. Output buffer layout: [T*B] outputs, then [B*2] final h.
//
// R8: __launch_bounds__(64, 1) so ptxas may use up to 255 regs — the R4 version
// was capped at 64 regs and spilled the prefetch buffers to local memory,
// putting LDL/STL on the serial recurrence chain (190us, all pipes idle).
// CH reduced 16->8 to keep total pressure ~110 regs.

#define TT 512
#define BB 32768
#define CH 8            // prefetch chunk (timesteps)
#define L2E 1.4426950408889634f

__device__ __forceinline__ float rcp_fast(float x) {
    float y; asm("rcp.approx.f32 %0, %1;" : "=f"(y) : "f"(x)); return y;
}
__device__ __forceinline__ float ex2_fast(float x) {
    float y; asm("ex2.approx.f32 %0, %1;" : "=f"(y) : "f"(x)); return y;
}
// sigmoid(a) = 1/(1+2^(-a*log2e)) : 2 MUFU, ~2^-22 accurate, saturates safely.
__device__ __forceinline__ float sigmoid_f(float a) {
    return rcp_fast(1.0f + ex2_fast(-L2E * a));
}
// tanh(a) = 2*sigmoid(2a)-1 : safe at extremes (no inf/inf), ~1e-7 abs err.
__device__ __forceinline__ float tanh_f(float a) {
    return fmaf(2.0f, rcp_fast(1.0f + ex2_fast(-2.0f * L2E * a)), -1.0f);
}

// PyTorch gate order in the 3H dim: rows 0,1 = r ; 2,3 = z ; 4,5 = n.
#define GRU_STEP(x0, x1, OIDX) do {                                   \
    /* off-chain: input projections (b_ih folded; r,z also get b_hh) */\
    float ur0  = fmaf(wi00, x0, fmaf(wi01, x1, bs0));                 \
    float ur1  = fmaf(wi10, x0, fmaf(wi11, x1, bs1));                 \
    float uz0  = fmaf(wi20, x0, fmaf(wi21, x1, bs2));                 \
    float uz1  = fmaf(wi30, x0, fmaf(wi31, x1, bs3));                 \
    float gin0 = fmaf(wi40, x0, fmaf(wi41, x1, bin0));                \
    float gin1 = fmaf(wi50, x0, fmaf(wi51, x1, bin1));                \
    /* on-chain: hidden projections */                                \
    float ar0  = fmaf(wh00, h0, fmaf(wh01, h1, ur0));                 \
    float ar1  = fmaf(wh10, h0, fmaf(wh11, h1, ur1));                 \
    float az0  = fmaf(wh20, h0, fmaf(wh21, h1, uz0));                 \
    float az1  = fmaf(wh30, h0, fmaf(wh31, h1, uz1));                 \
    float ghn0 = fmaf(wh40, h0, fmaf(wh41, h1, bhn0));                \
    float ghn1 = fmaf(wh50, h0, fmaf(wh51, h1, bhn1));                \
    float r0 = sigmoid_f(ar0);                                        \
    float r1 = sigmoid_f(ar1);                                        \
    float z0 = sigmoid_f(az0);                                        \
    float z1 = sigmoid_f(az1);                                        \
    float n0 = tanh_f(fmaf(r0, ghn0, gin0));                          \
    float n1 = tanh_f(fmaf(r1, ghn1, gin1));                          \
    /* h = (1-z)*n + z*h  ==  n + z*(h-n) */                          \
    h0 = fmaf(z0, h0 - n0, n0);                                       \
    h1 = fmaf(z1, h1 - n1, n1);                                       \
    /* out = exp(fc_w . h + fc_b) via ex2 with prescaled constants */ \
    out[(size_t)(OIDX) * BB + b] =                                    \
        ex2_fast(fmaf(fw0, h0, fmaf(fw1, h1, fb)));                   \
} while (0)

__global__ void __launch_bounds__(64, 1)
gru_scan_kernel(const float* __restrict__ x,
                const float* __restrict__ hx,
                const float* __restrict__ W_ih,
                const float* __restrict__ W_hh,
                const float* __restrict__ b_ih,
                const float* __restrict__ b_hh,
                const float* __restrict__ fc_w,
                const float* __restrict__ fc_b,
                float* __restrict__ out)
{
    const int b = blockIdx.x * 64 + threadIdx.x;   // batch lane

    // Uniform-address weight loads (broadcast, hit L1 after first warp).
    const float wi00 = W_ih[0],  wi01 = W_ih[1];
    const float wi10 = W_ih[2],  wi11 = W_ih[3];
    const float wi20 = W_ih[4],  wi21 = W_ih[5];
    const float wi30 = W_ih[6],  wi31 = W_ih[7];
    const float wi40 = W_ih[8],  wi41 = W_ih[9];
    const float wi50 = W_ih[10], wi51 = W_ih[11];

    const float wh00 = W_hh[0],  wh01 = W_hh[1];
    const float wh10 = W_hh[2],  wh11 = W_hh[3];
    const float wh20 = W_hh[4],  wh21 = W_hh[5];
    const float wh30 = W_hh[6],  wh31 = W_hh[7];
    const float wh40 = W_hh[8],  wh41 = W_hh[9];
    const float wh50 = W_hh[10], wh51 = W_hh[11];

    const float bs0  = b_ih[0] + b_hh[0];   // r0: biases fold into preact
    const float bs1  = b_ih[1] + b_hh[1];   // r1
    const float bs2  = b_ih[2] + b_hh[2];   // z0
    const float bs3  = b_ih[3] + b_hh[3];   // z1
    const float bin0 = b_ih[4], bin1 = b_ih[5];   // n: b_ih outside r*
    const float bhn0 = b_hh[4], bhn1 = b_hh[5];   // n: b_hh inside r*

    // exp(fc.h + fb) = 2^((fc.h + fb)*log2e) — prescale constants.
    const float fw0 = fc_w[0] * L2E;
    const float fw1 = fc_w[1] * L2E;
    const float fb  = fc_b[0] * L2E;

    const float2 hinit = reinterpret_cast<const float2*>(hx)[b];
    float h0 = hinit.x, h1 = hinit.y;

    const float2* __restrict__ x2 = reinterpret_cast<const float2*>(x);

    // Double-buffered register prefetch: hide ~600cyc DRAM latency behind
    // ~830cyc of compute per 8-step chunk. MLP=8 per thread.
    float2 bufA[CH], bufB[CH];
#pragma unroll
    for (int i = 0; i < CH; i++) bufA[i] = x2[(size_t)i * BB + b];

    for (int tc = 0; tc < TT; tc += 2 * CH) {
#pragma unroll
        for (int i = 0; i < CH; i++)
            bufB[i] = x2[(size_t)(tc + CH + i) * BB + b];

#pragma unroll
        for (int i = 0; i < CH; i++) {
            float x0 = bufA[i].x, x1 = bufA[i].y;
            GRU_STEP(x0, x1, tc + i);
        }

        if (tc + 2 * CH < TT) {
#pragma unroll
            for (int i = 0; i < CH; i++)
                bufA[i] = x2[(size_t)(tc + 2 * CH + i) * BB + b];
        }

#pragma unroll
        for (int i = 0; i < CH; i++) {
            float x0 = bufB[i].x, x1 = bufB[i].y;
            GRU_STEP(x0, x1, tc + CH + i);
        }
    }

    // Final hidden state appended after the [T*B] output block.
    reinterpret_cast<float2*>(out + (size_t)TT * BB)[b] = make_float2(h0, h1);
}

extern "C" void kernel_launch(void* const* d_in, const int* in_sizes, int n_in,
                              void* d_out, int out_size)
{
    const float* x    = (const float*)d_in[0];
    const float* hx   = (const float*)d_in[1];
    const float* W_ih = (const float*)d_in[2];
    const float* W_hh = (const float*)d_in[3];
    const float* b_ih = (const float*)d_in[4];
    const float* b_hh = (const float*)d_in[5];
    const float* fc_w = (const float*)d_in[6];
    const float* fc_b = (const float*)d_in[7];
    float* out = (float*)d_out;

    gru_scan_kernel<<<BB / 64, 64>>>(x, hx, W_ih, W_hh, b_ih, b_hh,
                                     fc_w, fc_b, out);
}

// round 12
// speedup vs baseline: 2.0499x; 1.3649x over previous
#include <cuda_runtime.h>

// GRU: I=2, H=2, T=512, B=32768, then out = exp(fc(h_t)) per step.
// One thread per batch lane; serial scan over T, double-buffered register
// prefetch of x. Output layout: [T*B] outputs, then [B*2] final h.
//
// R11: per-SMSP throughput model showed MUFU (13 ops/step x rt8 x 2 warps)
// and FMA (46/step) as the binds. This round:
//  - tanh.approx.f32 (1 MUFU) for r and n gates (error damped/compressed);
//    z gate + output exp stay accurate ex2+rcp (integrator path).
//  - fma.rn.f32x2 (FFMA2) packing for all gate-pair matvec preacts.
//  - running output pointer (no per-step address IMADs).

#define TT 512
#define BB 32768
#define CH 8
#define L2E 1.4426950408889634f

// ---- scalar fast ops ----
__device__ __forceinline__ float rcp_fast(float x) {
    float y; asm("rcp.approx.f32 %0, %1;" : "=f"(y) : "f"(x)); return y;
}
__device__ __forceinline__ float ex2_fast(float x) {
    float y; asm("ex2.approx.f32 %0, %1;" : "=f"(y) : "f"(x)); return y;
}
__device__ __forceinline__ float tanh_fast(float x) {
    float y; asm("tanh.approx.f32 %0, %1;" : "=f"(y) : "f"(x)); return y;
}
// accurate sigmoid (z gate): 1/(1+2^(-a*log2e)), ~2^-22.
__device__ __forceinline__ float sigmoid_acc(float a) {
    return rcp_fast(1.0f + ex2_fast(-L2E * a));
}

// ---- packed f32x2 ops ----
typedef unsigned long long u64;
__device__ __forceinline__ u64 pack2(float lo, float hi) {
    u64 r; asm("mov.b64 %0, {%1, %2};" : "=l"(r) : "f"(lo), "f"(hi)); return r;
}
__device__ __forceinline__ void unpack2(u64 v, float& lo, float& hi) {
    asm("mov.b64 {%0, %1}, %2;" : "=f"(lo), "=f"(hi) : "l"(v));
}
__device__ __forceinline__ u64 fma2(u64 a, u64 b, u64 c) {
    u64 d; asm("fma.rn.f32x2 %0, %1, %2, %3;" : "=l"(d) : "l"(a), "l"(b), "l"(c)); return d;
}
__device__ __forceinline__ u64 mul2(u64 a, u64 b) {
    u64 d; asm("mul.rn.f32x2 %0, %1, %2;" : "=l"(d) : "l"(a), "l"(b)); return d;
}

// One GRU step + output. Gate pairs packed as (unit0, unit1).
#define GRU_STEP(x0, x1) do {                                         \
    u64 xx0 = pack2(x0, x0);                                          \
    u64 xx1 = pack2(x1, x1);                                          \
    u64 hh0 = pack2(h0, h0);                                          \
    u64 hh1 = pack2(h1, h1);                                          \
    /* full preacts for r,z; split gi/gh for n */                     \
    u64 ar  = fma2(whr0, hh0, fma2(whr1, hh1,                         \
              fma2(wir0, xx0, fma2(wir1, xx1, bsR))));                \
    u64 az  = fma2(whz0, hh0, fma2(whz1, hh1,                         \
              fma2(wiz0, xx0, fma2(wiz1, xx1, bsZ))));                \
    u64 gin = fma2(win0, xx0, fma2(win1, xx1, binN));                 \
    u64 ghn = fma2(whn0, hh0, fma2(whn1, hh1, bhnN));                 \
    /* r via HW tanh: sigmoid(a)=0.5+0.5*tanh(0.5a) */                \
    float ar0, ar1, az0, az1, gin0, gin1, ghn0, ghn1;                 \
    u64 arh = mul2(ar, cHALF);                                        \
    unpack2(arh, ar0, ar1);                                           \
    unpack2(az, az0, az1);                                            \
    unpack2(gin, gin0, gin1);                                         \
    unpack2(ghn, ghn0, ghn1);                                         \
    float r0 = fmaf(0.5f, tanh_fast(ar0), 0.5f);                      \
    float r1 = fmaf(0.5f, tanh_fast(ar1), 0.5f);                      \
    float z0 = sigmoid_acc(az0);                                      \
    float z1 = sigmoid_acc(az1);                                      \
    float n0 = tanh_fast(fmaf(r0, ghn0, gin0));                       \
    float n1 = tanh_fast(fmaf(r1, ghn1, gin1));                       \
    h0 = fmaf(z0, h0 - n0, n0);                                       \
    h1 = fmaf(z1, h1 - n1, n1);                                       \
    *op = ex2_fast(fmaf(fw0, h0, fmaf(fw1, h1, fb)));                 \
    op += BB;                                                         \
} while (0)

__global__ void __launch_bounds__(64, 1)
gru_scan_kernel(const float* __restrict__ x,
                const float* __restrict__ hx,
                const float* __restrict__ W_ih,
                const float* __restrict__ W_hh,
                const float* __restrict__ b_ih,
                const float* __restrict__ b_hh,
                const float* __restrict__ fc_w,
                const float* __restrict__ fc_b,
                float* __restrict__ out)
{
    const int b = blockIdx.x * 64 + threadIdx.x;   // batch lane

    // Packed weight columns. Gate pair p in {r,z,n}: rows (2p, 2p+1).
    // w*0 = column 0 of both rows, w*1 = column 1.
    const u64 wir0 = pack2(W_ih[0],  W_ih[2]);
    const u64 wir1 = pack2(W_ih[1],  W_ih[3]);
    const u64 wiz0 = pack2(W_ih[4],  W_ih[6]);
    const u64 wiz1 = pack2(W_ih[5],  W_ih[7]);
    const u64 win0 = pack2(W_ih[8],  W_ih[10]);
    const u64 win1 = pack2(W_ih[9],  W_ih[11]);

    const u64 whr0 = pack2(W_hh[0],  W_hh[2]);
    const u64 whr1 = pack2(W_hh[1],  W_hh[3]);
    const u64 whz0 = pack2(W_hh[4],  W_hh[6]);
    const u64 whz1 = pack2(W_hh[5],  W_hh[7]);
    const u64 whn0 = pack2(W_hh[8],  W_hh[10]);
    const u64 whn1 = pack2(W_hh[9],  W_hh[11]);

    // Biases: r,z fold b_ih+b_hh; n keeps b_ih (outside r*) / b_hh (inside).
    const u64 bsR  = pack2(b_ih[0] + b_hh[0], b_ih[1] + b_hh[1]);
    const u64 bsZ  = pack2(b_ih[2] + b_hh[2], b_ih[3] + b_hh[3]);
    const u64 binN = pack2(b_ih[4], b_ih[5]);
    const u64 bhnN = pack2(b_hh[4], b_hh[5]);
    const u64 cHALF = pack2(0.5f, 0.5f);

    // exp(fc.h + fb) = 2^((fc.h + fb)*log2e) — prescale constants.
    const float fw0 = fc_w[0] * L2E;
    const float fw1 = fc_w[1] * L2E;
    const float fb  = fc_b[0] * L2E;

    const float2 hinit = reinterpret_cast<const float2*>(hx)[b];
    float h0 = hinit.x, h1 = hinit.y;

    const float2* __restrict__ x2 = reinterpret_cast<const float2*>(x);
    float* op = out + b;   // running output pointer (strength-reduced)

    // Double-buffered register prefetch: MLP=8/thread hides ~600cyc DRAM.
    float2 bufA[CH], bufB[CH];
#pragma unroll
    for (int i = 0; i < CH; i++) bufA[i] = x2[(size_t)i * BB + b];

    for (int tc = 0; tc < TT; tc += 2 * CH) {
#pragma unroll
        for (int i = 0; i < CH; i++)
            bufB[i] = x2[(size_t)(tc + CH + i) * BB + b];

#pragma unroll
        for (int i = 0; i < CH; i++)
            GRU_STEP(bufA[i].x, bufA[i].y);

        if (tc + 2 * CH < TT) {
#pragma unroll
            for (int i = 0; i < CH; i++)
                bufA[i] = x2[(size_t)(tc + 2 * CH + i) * BB + b];
        }

#pragma unroll
        for (int i = 0; i < CH; i++)
            GRU_STEP(bufB[i].x, bufB[i].y);
    }

    // Final hidden state appended after the [T*B] output block.
    reinterpret_cast<float2*>(out + (size_t)TT * BB)[b] = make_float2(h0, h1);
}

extern "C" void kernel_launch(void* const* d_in, const int* in_sizes, int n_in,
                              void* d_out, int out_size)
{
    const float* x    = (const float*)d_in[0];
    const float* hx   = (const float*)d_in[1];
    const float* W_ih = (const float*)d_in[2];
    const float* W_hh = (const float*)d_in[3];
    const float* b_ih = (const float*)d_in[4];
    const float* b_hh = (const float*)d_in[5];
    const float* fc_w = (const float*)d_in[6];
    const float* fc_b = (const float*)d_in[7];
    float* out = (float*)d_out;

    gru_scan_kernel<<<BB / 64, 64>>>(x, hx, W_ih, W_hh, b_ih, b_hh,
                                     fc_w, fc_b, out);
}

// round 14
// speedup vs baseline: 2.0950x; 1.0220x over previous
#include <cuda_runtime.h>

// GRU: I=2, H=2, T=512, B=32768, then out = exp(fc(h_t)) per step.
// One thread per batch lane; serial scan over T, double-buffered register
// prefetch of x. Output layout: [T*B] outputs, then [B*2] final h.
//
// R12: all three gates on HW tanh.approx (1 MUFU each) via the identity
// sigmoid(a) = 0.5 + 0.5*tanh(a/2), with the /2 pre-folded into the weight
// constants (r,z fully; n's hidden branch as ghn' = 0.5*ghn so that
// n_pre = (gin + ghn') + tanh(ar')*ghn' = gin + r*ghn exactly).
// MUFU/step 9 -> 7; z chain 36 -> 16 cyc. Output exp stays accurate ex2.

#define TT 512
#define BB 32768
#define CH 8
#define L2E 1.4426950408889634f

// ---- scalar fast ops ----
__device__ __forceinline__ float ex2_fast(float x) {
    float y; asm("ex2.approx.f32 %0, %1;" : "=f"(y) : "f"(x)); return y;
}
__device__ __forceinline__ float tanh_fast(float x) {
    float y; asm("tanh.approx.f32 %0, %1;" : "=f"(y) : "f"(x)); return y;
}

// ---- packed f32x2 ops ----
typedef unsigned long long u64;
__device__ __forceinline__ u64 pack2(float lo, float hi) {
    u64 r; asm("mov.b64 %0, {%1, %2};" : "=l"(r) : "f"(lo), "f"(hi)); return r;
}
__device__ __forceinline__ void unpack2(u64 v, float& lo, float& hi) {
    asm("mov.b64 {%0, %1}, %2;" : "=f"(lo), "=f"(hi) : "l"(v));
}
__device__ __forceinline__ u64 fma2(u64 a, u64 b, u64 c) {
    u64 d; asm("fma.rn.f32x2 %0, %1, %2, %3;" : "=l"(d) : "l"(a), "l"(b), "l"(c)); return d;
}
__device__ __forceinline__ u64 add2(u64 a, u64 b) {
    u64 d; asm("add.rn.f32x2 %0, %1, %2;" : "=l"(d) : "l"(a), "l"(b)); return d;
}

// One GRU step + output. Gate pairs packed as (unit0, unit1).
// w?r/w?z/whn/bsR/bsZ/bhnN are PRE-HALVED; win/binN are full scale.
#define GRU_STEP(x0, x1) do {                                         \
    u64 xx0 = pack2(x0, x0);                                          \
    u64 xx1 = pack2(x1, x1);                                          \
    u64 hh0 = pack2(h0, h0);                                          \
    u64 hh1 = pack2(h1, h1);                                          \
    u64 ar  = fma2(whr0, hh0, fma2(whr1, hh1,                         \
              fma2(wir0, xx0, fma2(wir1, xx1, bsR))));    /* 0.5*pre */\
    u64 az  = fma2(whz0, hh0, fma2(whz1, hh1,                         \
              fma2(wiz0, xx0, fma2(wiz1, xx1, bsZ))));    /* 0.5*pre */\
    u64 gh  = fma2(whn0, hh0, fma2(whn1, hh1, bhnN));     /* 0.5*ghn */\
    u64 gi  = fma2(win0, xx0, fma2(win1, xx1, binN));     /* full    */\
    u64 nb  = add2(gi, gh);                    /* gin + 0.5*ghn      */\
    float ar0, ar1, az0, az1, gh0, gh1, nb0, nb1;                     \
    unpack2(ar, ar0, ar1);                                            \
    unpack2(az, az0, az1);                                            \
    unpack2(gh, gh0, gh1);                                            \
    unpack2(nb, nb0, nb1);                                            \
    float tr0 = tanh_fast(ar0);                                       \
    float tr1 = tanh_fast(ar1);                                       \
    /* n = tanh(gin + r*ghn), r = 0.5+0.5*tr  ->  nb + tr*gh */       \
    float n0 = tanh_fast(fmaf(tr0, gh0, nb0));                        \
    float n1 = tanh_fast(fmaf(tr1, gh1, nb1));                        \
    float tz0 = tanh_fast(az0);                                       \
    float tz1 = tanh_fast(az1);                                       \
    /* h = (1-z)n + z h, z = 0.5+0.5*tz -> 0.5(h+n) + 0.5*tz*(h-n) */ \
    float s0 = h0 + n0, d0 = h0 - n0;                                 \
    float s1 = h1 + n1, d1 = h1 - n1;                                 \
    h0 = fmaf(0.5f * tz0, d0, 0.5f * s0);                             \
    h1 = fmaf(0.5f * tz1, d1, 0.5f * s1);                             \
    *op = ex2_fast(fmaf(fw0, h0, fmaf(fw1, h1, fb)));                 \
    op += BB;                                                         \
} while (0)

__global__ void __launch_bounds__(64, 1)
gru_scan_kernel(const float* __restrict__ x,
                const float* __restrict__ hx,
                const float* __restrict__ W_ih,
                const float* __restrict__ W_hh,
                const float* __restrict__ b_ih,
                const float* __restrict__ b_hh,
                const float* __restrict__ fc_w,
                const float* __restrict__ fc_b,
                float* __restrict__ out)
{
    const int b = blockIdx.x * 64 + threadIdx.x;   // batch lane

    // Packed weight columns, gate pair p in {r,z,n}: rows (2p, 2p+1).
    // r,z and n-hidden branches are PRE-HALVED for the tanh-sigmoid identity.
    const u64 wir0 = pack2(0.5f * W_ih[0],  0.5f * W_ih[2]);
    const u64 wir1 = pack2(0.5f * W_ih[1],  0.5f * W_ih[3]);
    const u64 wiz0 = pack2(0.5f * W_ih[4],  0.5f * W_ih[6]);
    const u64 wiz1 = pack2(0.5f * W_ih[5],  0.5f * W_ih[7]);
    const u64 win0 = pack2(W_ih[8],  W_ih[10]);
    const u64 win1 = pack2(W_ih[9],  W_ih[11]);

    const u64 whr0 = pack2(0.5f * W_hh[0],  0.5f * W_hh[2]);
    const u64 whr1 = pack2(0.5f * W_hh[1],  0.5f * W_hh[3]);
    const u64 whz0 = pack2(0.5f * W_hh[4],  0.5f * W_hh[6]);
    const u64 whz1 = pack2(0.5f * W_hh[5],  0.5f * W_hh[7]);
    const u64 whn0 = pack2(0.5f * W_hh[8],  0.5f * W_hh[10]);
    const u64 whn1 = pack2(0.5f * W_hh[9],  0.5f * W_hh[11]);

    // Biases: r,z fold (b_ih+b_hh)/2; n keeps b_ih full (outside r*) and
    // b_hh/2 (inside r*, as part of ghn').
    const u64 bsR  = pack2(0.5f * (b_ih[0] + b_hh[0]),
                           0.5f * (b_ih[1] + b_hh[1]));
    const u64 bsZ  = pack2(0.5f * (b_ih[2] + b_hh[2]),
                           0.5f * (b_ih[3] + b_hh[3]));
    const u64 binN = pack2(b_ih[4], b_ih[5]);
    const u64 bhnN = pack2(0.5f * b_hh[4], 0.5f * b_hh[5]);

    // exp(fc.h + fb) = 2^((fc.h + fb)*log2e) — prescale constants.
    const float fw0 = fc_w[0] * L2E;
    const float fw1 = fc_w[1] * L2E;
    const float fb  = fc_b[0] * L2E;

    const float2 hinit = reinterpret_cast<const float2*>(hx)[b];
    float h0 = hinit.x, h1 = hinit.y;

    const float2* __restrict__ x2 = reinterpret_cast<const float2*>(x);
    float* op = out + b;   // running output pointer

    // Double-buffered register prefetch: MLP=8/thread hides ~600cyc DRAM.
    float2 bufA[CH], bufB[CH];
#pragma unroll
    for (int i = 0; i < CH; i++) bufA[i] = x2[(size_t)i * BB + b];

    for (int tc = 0; tc < TT; tc += 2 * CH) {
#pragma unroll
        for (int i = 0; i < CH; i++)
            bufB[i] = x2[(size_t)(tc + CH + i) * BB + b];

#pragma unroll
        for (int i = 0; i < CH; i++)
            GRU_STEP(bufA[i].x, bufA[i].y);

        if (tc + 2 * CH < TT) {
#pragma unroll
            for (int i = 0; i < CH; i++)
                bufA[i] = x2[(size_t)(tc + 2 * CH + i) * BB + b];
        }

#pragma unroll
        for (int i = 0; i < CH; i++)
            GRU_STEP(bufB[i].x, bufB[i].y);
    }

    // Final hidden state appended after the [T*B] output block.
    reinterpret_cast<float2*>(out + (size_t)TT * BB)[b] = make_float2(h0, h1);
}

extern "C" void kernel_launch(void* const* d_in, const int* in_sizes, int n_in,
                              void* d_out, int out_size)
{
    const float* x    = (const float*)d_in[0];
    const float* hx   = (const float*)d_in[1];
    const float* W_ih = (const float*)d_in[2];
    const float* W_hh = (const float*)d_in[3];
    const float* b_ih = (const float*)d_in[4];
    const float* b_hh = (const float*)d_in[5];
    const float* fc_w = (const float*)d_in[6];
    const float* fc_b = (const float*)d_in[7];
    float* out = (float*)d_out;

    gru_scan_kernel<<<BB / 64, 64>>>(x, hx, W_ih, W_hh, b_ih, b_hh,
                                     fc_w, fc_b, out);
}

// round 17
// speedup vs baseline: 2.5758x; 1.2295x over previous
#include <cuda_runtime.h>

// GRU: I=2, H=2, T=512, B=32768, then out = exp(fc(h_t)) per step.
// One thread per batch lane; serial scan over T, double-buffered register
// prefetch of x. Output layout: [T*B] outputs, then [B*2] final h.
//
// R14: block 64 -> 128. B300 maps warp wid%4 -> SMSP; a 64-thread block has
// warps 0,1 only => every block concentrated on SMSPs 0/1, leaving SMSPs 2/3
// idle (explains flat R12 and "fma=34%" = ~68% on the active half). 128-thread
// blocks cover all 4 SMSPs; grid 256 => uniform ~2 warps/SMSP.

#define TT 512
#define BB 32768
#define CH 8
#define L2E 1.4426950408889634f

// ---- scalar fast ops ----
__device__ __forceinline__ float ex2_fast(float x) {
    float y; asm("ex2.approx.f32 %0, %1;" : "=f"(y) : "f"(x)); return y;
}
__device__ __forceinline__ float tanh_fast(float x) {
    float y; asm("tanh.approx.f32 %0, %1;" : "=f"(y) : "f"(x)); return y;
}

// ---- packed f32x2 ops ----
typedef unsigned long long u64;
__device__ __forceinline__ u64 pack2(float lo, float hi) {
    u64 r; asm("mov.b64 %0, {%1, %2};" : "=l"(r) : "f"(lo), "f"(hi)); return r;
}
__device__ __forceinline__ void unpack2(u64 v, float& lo, float& hi) {
    asm("mov.b64 {%0, %1}, %2;" : "=f"(lo), "=f"(hi) : "l"(v));
}
__device__ __forceinline__ u64 fma2(u64 a, u64 b, u64 c) {
    u64 d; asm("fma.rn.f32x2 %0, %1, %2, %3;" : "=l"(d) : "l"(a), "l"(b), "l"(c)); return d;
}
__device__ __forceinline__ u64 add2(u64 a, u64 b) {
    u64 d; asm("add.rn.f32x2 %0, %1, %2;" : "=l"(d) : "l"(a), "l"(b)); return d;
}

// One GRU step + output. Gate pairs packed as (unit0, unit1).
// w?r/w?z/whn/bsR/bsZ/bhnN are PRE-HALVED; win/binN are full scale.
#define GRU_STEP(x0, x1) do {                                         \
    u64 xx0 = pack2(x0, x0);                                          \
    u64 xx1 = pack2(x1, x1);                                          \
    u64 hh0 = pack2(h0, h0);                                          \
    u64 hh1 = pack2(h1, h1);                                          \
    u64 ar  = fma2(whr0, hh0, fma2(whr1, hh1,                         \
              fma2(wir0, xx0, fma2(wir1, xx1, bsR))));    /* 0.5*pre */\
    u64 az  = fma2(whz0, hh0, fma2(whz1, hh1,                         \
              fma2(wiz0, xx0, fma2(wiz1, xx1, bsZ))));    /* 0.5*pre */\
    u64 gh  = fma2(whn0, hh0, fma2(whn1, hh1, bhnN));     /* 0.5*ghn */\
    u64 gi  = fma2(win0, xx0, fma2(win1, xx1, binN));     /* full    */\
    u64 nb  = add2(gi, gh);                    /* gin + 0.5*ghn      */\
    float ar0, ar1, az0, az1, gh0, gh1, nb0, nb1;                     \
    unpack2(ar, ar0, ar1);                                            \
    unpack2(az, az0, az1);                                            \
    unpack2(gh, gh0, gh1);                                            \
    unpack2(nb, nb0, nb1);                                            \
    float tr0 = tanh_fast(ar0);                                       \
    float tr1 = tanh_fast(ar1);                                       \
    /* n = tanh(gin + r*ghn), r = 0.5+0.5*tr  ->  nb + tr*gh */       \
    float n0 = tanh_fast(fmaf(tr0, gh0, nb0));                        \
    float n1 = tanh_fast(fmaf(tr1, gh1, nb1));                        \
    float tz0 = tanh_fast(az0);                                       \
    float tz1 = tanh_fast(az1);                                       \
    /* h = (1-z)n + z h, z = 0.5+0.5*tz -> 0.5(h+n) + 0.5*tz*(h-n) */ \
    float s0 = h0 + n0, d0 = h0 - n0;                                 \
    float s1 = h1 + n1, d1 = h1 - n1;                                 \
    h0 = fmaf(0.5f * tz0, d0, 0.5f * s0);                             \
    h1 = fmaf(0.5f * tz1, d1, 0.5f * s1);                             \
    *op = ex2_fast(fmaf(fw0, h0, fmaf(fw1, h1, fb)));                 \
    op += BB;                                                         \
} while (0)

__global__ void __launch_bounds__(128, 1)
gru_scan_kernel(const float* __restrict__ x,
                const float* __restrict__ hx,
                const float* __restrict__ W_ih,
                const float* __restrict__ W_hh,
                const float* __restrict__ b_ih,
                const float* __restrict__ b_hh,
                const float* __restrict__ fc_w,
                const float* __restrict__ fc_b,
                float* __restrict__ out)
{
    const int b = blockIdx.x * 128 + threadIdx.x;   // batch lane

    // Packed weight columns, gate pair p in {r,z,n}: rows (2p, 2p+1).
    // r,z and n-hidden branches are PRE-HALVED for the tanh-sigmoid identity.
    const u64 wir0 = pack2(0.5f * W_ih[0],  0.5f * W_ih[2]);
    const u64 wir1 = pack2(0.5f * W_ih[1],  0.5f * W_ih[3]);
    const u64 wiz0 = pack2(0.5f * W_ih[4],  0.5f * W_ih[6]);
    const u64 wiz1 = pack2(0.5f * W_ih[5],  0.5f * W_ih[7]);
    const u64 win0 = pack2(W_ih[8],  W_ih[10]);
    const u64 win1 = pack2(W_ih[9],  W_ih[11]);

    const u64 whr0 = pack2(0.5f * W_hh[0],  0.5f * W_hh[2]);
    const u64 whr1 = pack2(0.5f * W_hh[1],  0.5f * W_hh[3]);
    const u64 whz0 = pack2(0.5f * W_hh[4],  0.5f * W_hh[6]);
    const u64 whz1 = pack2(0.5f * W_hh[5],  0.5f * W_hh[7]);
    const u64 whn0 = pack2(0.5f * W_hh[8],  0.5f * W_hh[10]);
    const u64 whn1 = pack2(0.5f * W_hh[9],  0.5f * W_hh[11]);

    // Biases: r,z fold (b_ih+b_hh)/2; n keeps b_ih full (outside r*) and
    // b_hh/2 (inside r*, as part of ghn').
    const u64 bsR  = pack2(0.5f * (b_ih[0] + b_hh[0]),
                           0.5f * (b_ih[1] + b_hh[1]));
    const u64 bsZ  = pack2(0.5f * (b_ih[2] + b_hh[2]),
                           0.5f * (b_ih[3] + b_hh[3]));
    const u64 binN = pack2(b_ih[4], b_ih[5]);
    const u64 bhnN = pack2(0.5f * b_hh[4], 0.5f * b_hh[5]);

    // exp(fc.h + fb) = 2^((fc.h + fb)*log2e) — prescale constants.
    const float fw0 = fc_w[0] * L2E;
    const float fw1 = fc_w[1] * L2E;
    const float fb  = fc_b[0] * L2E;

    const float2 hinit = reinterpret_cast<const float2*>(hx)[b];
    float h0 = hinit.x, h1 = hinit.y;

    const float2* __restrict__ x2 = reinterpret_cast<const float2*>(x);
    float* op = out + b;   // running output pointer

    // Double-buffered register prefetch: MLP=8/thread hides ~600cyc DRAM.
    float2 bufA[CH], bufB[CH];
#pragma unroll
    for (int i = 0; i < CH; i++) bufA[i] = x2[(size_t)i * BB + b];

    for (int tc = 0; tc < TT; tc += 2 * CH) {
#pragma unroll
        for (int i = 0; i < CH; i++)
            bufB[i] = x2[(size_t)(tc + CH + i) * BB + b];

#pragma unroll
        for (int i = 0; i < CH; i++)
            GRU_STEP(bufA[i].x, bufA[i].y);

        if (tc + 2 * CH < TT) {
#pragma unroll
            for (int i = 0; i < CH; i++)
                bufA[i] = x2[(size_t)(tc + 2 * CH + i) * BB + b];
        }

#pragma unroll
        for (int i = 0; i < CH; i++)
            GRU_STEP(bufB[i].x, bufB[i].y);
    }

    // Final hidden state appended after the [T*B] output block.
    reinterpret_cast<float2*>(out + (size_t)TT * BB)[b] = make_float2(h0, h1);
}

extern "C" void kernel_launch(void* const* d_in, const int* in_sizes, int n_in,
                              void* d_out, int out_size)
{
    const float* x    = (const float*)d_in[0];
    const float* hx   = (const float*)d_in[1];
    const float* W_ih = (const float*)d_in[2];
    const float* W_hh = (const float*)d_in[3];
    const float* b_ih = (const float*)d_in[4];
    const float* b_hh = (const float*)d_in[5];
    const float* fc_w = (const float*)d_in[6];
    const float* fc_b = (const float*)d_in[7];
    float* out = (float*)d_out;

    gru_scan_kernel<<<BB / 128, 128>>>(x, hx, W_ih, W_hh, b_ih, b_hh,
                                       fc_w, fc_b, out);
}